// round 16
// baseline (speedup 1.0000x reference)
#include <cuda_runtime.h>
#include <cuda_fp16.h>
#include <math.h>
#include <stdint.h>

#define BB 32
#define VV 16
#define LL 64
#define PP 64
#define DD 64
#define NTOK 32768      // BB*VV*LL
#define NQ 8
#define BINS 1024
#define EPSF 1e-5f
#define TPAD 66

#define ZQ_OFF   (NTOK*DD)           // 2097152
#define CODES_N  (NQ*NTOK)           // 262144

typedef unsigned long long ull;

// m16n8k16 f16 mma, fp32 accum (sm_80+; legal under compute_100)
__device__ __forceinline__ void mma_f16(float* c, const uint32_t* a,
                                        uint32_t b0, uint32_t b1) {
    asm volatile("mma.sync.aligned.m16n8k16.row.col.f32.f16.f16.f32 "
        "{%0,%1,%2,%3}, {%4,%5,%6,%7}, {%8,%9}, {%0,%1,%2,%3};"
        : "+f"(c[0]), "+f"(c[1]), "+f"(c[2]), "+f"(c[3])
        : "r"(a[0]), "r"(a[1]), "r"(a[2]), "r"(a[3]), "r"(b0), "r"(b1));
}

__device__ __forceinline__ uint32_t pack_h2(float x, float y) {
    __half2 h = __floats2half2_rn(x, y);
    return *reinterpret_cast<uint32_t*>(&h);
}

// fp32x2 helpers for k_enc (lowered to 2x FFMA on sm_100; harmless)
__device__ __forceinline__ void fma2(ull& acc, ull a, ull b) {
    asm("fma.rn.f32x2 %0, %1, %2, %0;" : "+l"(acc) : "l"(a), "l"(b));
}
__device__ __forceinline__ float unpack_sum(ull a) {
    float2 p = *reinterpret_cast<float2*>(&a);
    return p.x + p.y;
}

// ---------------- scratch (device globals; no allocation allowed) -------------
__device__ __align__(16) float  g_z[NTOK*DD];
__device__ __align__(16) float  g_zh[NTOK*DD];
// fp16 hi/lo fragment codebook: F = (((q*16+ch)*8+nt)*4+s)*32+lane
// uint4 = {bhi0, bhi1, blo0, blo1}
__device__ __align__(16) uint4  g_cbf16[NQ*16*8*4*32];   // 131072 uint4 = 2 MB
__device__ float    g_cbsq[NQ*BINS];
__device__ double   g_sum[LL], g_sumsq[LL];
__device__ double   g_colnorm[BB*DD];
__device__ double   g_loss[NQ];
__device__ unsigned g_done;

// ---------------- k_prep: codebook norms + fp16 fragments + zeroing -----------
__global__ void k_prep(const float* __restrict__ cb) {
    int tid = threadIdx.x;
    int F = blockIdx.x*256 + tid;
    {   // fp16 hi/lo fragment
        int lane = F & 31;
        int s    = (F >> 5) & 3;
        int nt   = (F >> 7) & 7;
        int ch   = (F >> 10) & 15;
        int q    = F >> 14;
        int g    = lane >> 2, tig = lane & 3;
        int entry = ch*64 + nt*8 + g;
        int k0 = 16*s + 2*tig;
        const float* src = cb + ((size_t)q*BINS + entry)*64;
        float v0 = src[k0],     v1 = src[k0+1];
        float v2 = src[k0+8],   v3 = src[k0+9];
        float h0 = __half2float(__float2half_rn(v0));
        float h1 = __half2float(__float2half_rn(v1));
        float h2 = __half2float(__float2half_rn(v2));
        float h3 = __half2float(__float2half_rn(v3));
        uint4 o;
        o.x = pack_h2(h0, h1);
        o.y = pack_h2(h2, h3);
        o.z = pack_h2(v0 - h0, v1 - h1);
        o.w = pack_h2(v2 - h2, v3 - h3);
        g_cbf16[F] = o;
    }
    if (blockIdx.x < 128) {   // squared norms, 64 rows/block, 4 thr/row
        int row = blockIdx.x*64 + (tid >> 2);
        const float* p = cb + (size_t)row*64 + (tid & 3)*16;
        float s = 0.f;
        #pragma unroll
        for (int i = 0; i < 16; i++) { float v = p[i]; s += v*v; }
        s += __shfl_xor_sync(0xffffffffu, s, 1);
        s += __shfl_xor_sync(0xffffffffu, s, 2);
        if ((tid & 3) == 0) g_cbsq[row] = s;
    }
    if (blockIdx.x < 8) g_colnorm[blockIdx.x*256 + tid] = 0.0;
    if (blockIdx.x == 0) {
        if (tid < LL) { g_sum[tid] = 0.0; g_sumsq[tid] = 0.0; }
        if (tid < NQ) g_loss[tid] = 0.0;
        if (tid == 0) g_done = 0u;
    }
}

// ---------------- k_fft: 64-pt DFT magnitude + fused per-l stats --------------
__global__ void __launch_bounds__(1024) k_fft(const float* __restrict__ x) {
    __shared__ float xs[PP*VV];
    __shared__ float ct[64], st[64];
    __shared__ float mags[VV*33];
    __shared__ float redp[64];
    int bi = blockIdx.x;
    int b = bi >> 6, l = bi & 63;
    int tid = threadIdx.x;
    xs[tid] = x[(size_t)(b*4096 + l*64)*16 + tid];
    if (tid < 64) { float a = (float)tid * (1.0f/32.0f); ct[tid] = cospif(a); st[tid] = sinpif(a); }
    __syncthreads();
    if (tid < 528) {
        int v = tid / 33, kk = tid % 33;
        float re = 0.f, im = 0.f;
        #pragma unroll 16
        for (int j = 0; j < 64; j++) {
            float val = xs[j*16 + v];
            int a = (j*kk) & 63;
            re += val * ct[a];
            im += val * st[a];
        }
        mags[v*33 + kk] = sqrtf(re*re + im*im);
    }
    __syncthreads();
    int v = tid >> 6, k = tid & 63;
    int kk = (k <= 32) ? k : (64 - k);
    float mag = mags[v*33 + kk];
    int t = (b*VV + v)*LL + l;
    g_z[t*64 + k] = mag;
    float s = mag, ss = mag*mag;
    #pragma unroll
    for (int o = 16; o; o >>= 1) {
        s  += __shfl_xor_sync(0xffffffffu, s, o);
        ss += __shfl_xor_sync(0xffffffffu, ss, o);
    }
    int wid = tid >> 5, lane = tid & 31;
    if (lane == 0) { redp[wid] = s; redp[32 + wid] = ss; }
    __syncthreads();
    if (tid < 32) {
        float s2 = redp[tid], ss2 = redp[32 + tid];
        #pragma unroll
        for (int o = 16; o; o >>= 1) {
            s2  += __shfl_xor_sync(0xffffffffu, s2, o);
            ss2 += __shfl_xor_sync(0xffffffffu, ss2, o);
        }
        if (tid == 0) {
            atomicAdd(&g_sum[l], (double)s2);
            atomicAdd(&g_sumsq[l], (double)ss2);
        }
    }
}

// helper: per-l mean / (std+eps) from accumulated double sums (ddof=1)
__device__ __forceinline__ void stat_ml(int l, float& mean_out, float& spe_out) {
    double n = 32768.0;
    double s = g_sum[l], ss = g_sumsq[l];
    double mean = s / n;
    double var = (ss - s*s/n) / (n - 1.0);
    mean_out = (float)mean;
    spe_out = (float)sqrt(var) + EPSF;
}

// ---------------- k_enc: encoder GEMM + per-(b,e) column norms ----------------
__global__ void __launch_bounds__(256, 2) k_enc(const float* __restrict__ ew,
                                                const float* __restrict__ eb) {
    extern __shared__ float sm[];
    float* zS   = sm;               // 128*TPAD
    float* wS   = zS + 128*TPAD;    // 64*TPAD
    float* red  = wS + 64*TPAD;     // 64*17
    float* meanS= red + 64*17;      // 64
    float* sinvS= meanS + 64;       // 64
    float* ebS  = sinvS + 64;       // 64

    int tid = threadIdx.x;
    int t0 = blockIdx.x * 128;

    if (tid < 64) {
        float mn, sp; stat_ml(tid, mn, sp);
        meanS[tid] = mn; sinvS[tid] = 1.0f / sp; ebS[tid] = eb[tid];
    }
    {
        const float4* w4 = (const float4*)ew;
        #pragma unroll
        for (int i = 0; i < 4; i++) {
            int f = tid + i*256;
            int e = f >> 4, d4 = f & 15;
            float4 v = w4[f];
            float* dst = wS + e*TPAD + d4*4;
            dst[0]=v.x; dst[1]=v.y; dst[2]=v.z; dst[3]=v.w;
        }
    }
    __syncthreads();
    {
        const float4* z4 = (const float4*)g_z + (size_t)t0*16;
        #pragma unroll
        for (int i = 0; i < 8; i++) {
            int f = tid + i*256;
            int t = f >> 4, d4 = f & 15;
            float4 v = z4[f];
            int l = (t0 + t) & 63;
            float m = meanS[l], si = sinvS[l];
            float* dst = zS + t*TPAD + d4*4;
            dst[0]=(v.x-m)*si; dst[1]=(v.y-m)*si; dst[2]=(v.z-m)*si; dst[3]=(v.w-m)*si;
        }
    }
    __syncthreads();

    int ty = tid >> 4, tx = tid & 15;
    ull acc2[8][4];
    #pragma unroll
    for (int i = 0; i < 8; i++)
        #pragma unroll
        for (int j = 0; j < 4; j++) acc2[i][j] = 0ull;

    #pragma unroll 8
    for (int d = 0; d < 64; d += 2) {
        ull rv[8], cv[4];
        #pragma unroll
        for (int i = 0; i < 8; i++) rv[i] = *(const ull*)(zS + (ty*8+i)*TPAD + d);
        #pragma unroll
        for (int j = 0; j < 4; j++) cv[j] = *(const ull*)(wS + (j*16+tx)*TPAD + d);
        #pragma unroll
        for (int i = 0; i < 8; i++)
            #pragma unroll
            for (int j = 0; j < 4; j++) fma2(acc2[i][j], rv[i], cv[j]);
    }

    float pn[4] = {0.f,0.f,0.f,0.f};
    #pragma unroll
    for (int i = 0; i < 8; i++) {
        int t = t0 + ty*8 + i;
        #pragma unroll
        for (int j = 0; j < 4; j++) {
            int e = j*16 + tx;
            float o = unpack_sum(acc2[i][j]) + ebS[e];
            pn[j] += o*o;
            g_zh[(size_t)t*64 + e] = o;
        }
    }
    #pragma unroll
    for (int j = 0; j < 4; j++) red[(j*16+tx)*17 + ty] = pn[j];
    __syncthreads();
    if (tid < 64) {
        float s = 0.f;
        #pragma unroll
        for (int y = 0; y < 16; y++) s += red[tid*17 + y];
        atomicAdd(&g_colnorm[(t0 >> 10)*64 + tid], (double)s);
    }
}

// ============================ k_rvq: fp16x3 mma RVQ ============================
// 256 blocks x 256 threads (8 warps), 2 blocks/SM. B fragments are read
// DIRECTLY from global (L1/L2-resident, warp-coalesced 512B) — no smem staging,
// no double buffering, NO per-chunk barriers. Warps free-run across the stage,
// so one warp's scalar argmin epilogue overlaps other warps' mma bursts (the
// barrier convoy that capped tensor at ~52% is gone). 2 barriers per stage only.
// Residual in registers (m16n8k16 A-fragment layout). QO = R_init - R_final.

// smem float offsets (overlay: stage view / decode view)
#define F_CSQ   0                  // stage view: 1024
#define F_QO    0                  // decode: 128*66 = 8448
#define F_DW    8448               // decode: 64*66 = 4224 -> ends 12672
#define F_FIX   12672
#define F_INV   (F_FIX)
#define F_MEAN  (F_FIX+64)
#define F_SPE   (F_FIX+128)
#define F_DB    (F_FIX+192)
#define F_LOSS  (F_FIX+256)        // 8
#define RVQ_SMEMF (F_FIX+272)
#define RVQ_SMEM  (RVQ_SMEMF*4)    // ~51.8 KB -> 2 blocks/SM

__global__ void __launch_bounds__(256, 2) k_rvq(const float* __restrict__ cb,
                                                const float* __restrict__ dw,
                                                const float* __restrict__ db,
                                                float* __restrict__ out) {
    extern __shared__ float sm[];
    float* csqS  = sm + F_CSQ;
    float* invS  = sm + F_INV;
    float* meanS = sm + F_MEAN;
    float* speS  = sm + F_SPE;
    float* dbS   = sm + F_DB;
    float* lossW = sm + F_LOSS;

    int tid = threadIdx.x;
    int w = tid >> 5, lane = tid & 31;
    int g = lane >> 2, tig = lane & 3;
    int t0 = blockIdx.x * 128;
    int b  = t0 >> 10;

    if (tid < 64) {
        invS[tid] = 1.0f / sqrtf((float)g_colnorm[b*64 + tid]);
        float mn, sp; stat_ml(tid, mn, sp);
        meanS[tid] = mn; speS[tid] = sp;
        dbS[tid]   = db[tid];
    }
    __syncthreads();

    int m0l = 16*w + g, m1l = m0l + 8;
    int m0g = t0 + m0l, m1g = t0 + m1l;

    // residual registers in A-fragment layout:
    // R[s*4+j]: k = 16s + 2tig + (j&1) + 8*(j>>1)
    float R0[16], R1[16];
    {
        const float* z0 = g_zh + (size_t)m0g*64;
        const float* z1 = g_zh + (size_t)m1g*64;
        #pragma unroll
        for (int s = 0; s < 4; s++) {
            int ka = 16*s + 2*tig;
            float2 a0 = *(const float2*)(z0 + ka);
            float2 b0 = *(const float2*)(z0 + ka + 8);
            float2 a1 = *(const float2*)(z1 + ka);
            float2 b1 = *(const float2*)(z1 + ka + 8);
            R0[s*4+0] = a0.x * invS[ka];     R0[s*4+1] = a0.y * invS[ka+1];
            R0[s*4+2] = b0.x * invS[ka+8];   R0[s*4+3] = b0.y * invS[ka+9];
            R1[s*4+0] = a1.x * invS[ka];     R1[s*4+1] = a1.y * invS[ka+1];
            R1[s*4+2] = b1.x * invS[ka+8];   R1[s*4+3] = b1.y * invS[ka+9];
        }
    }

    for (int q = 0; q < NQ; q++) {
        // A hi/lo fragments for this stage
        uint32_t AH[4][4], AL[4][4];
        #pragma unroll
        for (int s = 0; s < 4; s++) {
            float h00 = __half2float(__float2half_rn(R0[s*4+0]));
            float h01 = __half2float(__float2half_rn(R0[s*4+1]));
            float h02 = __half2float(__float2half_rn(R0[s*4+2]));
            float h03 = __half2float(__float2half_rn(R0[s*4+3]));
            float h10 = __half2float(__float2half_rn(R1[s*4+0]));
            float h11 = __half2float(__float2half_rn(R1[s*4+1]));
            float h12 = __half2float(__float2half_rn(R1[s*4+2]));
            float h13 = __half2float(__float2half_rn(R1[s*4+3]));
            AH[s][0] = pack_h2(h00, h01);
            AH[s][1] = pack_h2(h10, h11);
            AH[s][2] = pack_h2(h02, h03);
            AH[s][3] = pack_h2(h12, h13);
            AL[s][0] = pack_h2(R0[s*4+0]-h00, R0[s*4+1]-h01);
            AL[s][1] = pack_h2(R1[s*4+0]-h10, R1[s*4+1]-h11);
            AL[s][2] = pack_h2(R0[s*4+2]-h02, R0[s*4+3]-h03);
            AL[s][3] = pack_h2(R1[s*4+2]-h12, R1[s*4+3]-h13);
        }

        __syncthreads();   // previous-stage csq consumers done
        #pragma unroll
        for (int i = 0; i < 4; i++) csqS[tid + i*256] = g_cbsq[q*BINS + tid + i*256];
        __syncthreads();

        float best0 = INFINITY, best1 = INFINITY;
        int idx0 = 0, idx1 = 0;

        // -------- barrier-free mainloop: B fragments straight from L1/L2 -----
        const uint4* gq = g_cbf16 + (size_t)q*16*1024 + lane;
        for (int ch = 0; ch < 16; ch++) {
            const uint4* gsrc = gq + ch*1024;

            float C[8][4];
            #pragma unroll
            for (int nt = 0; nt < 8; nt++)
                #pragma unroll
                for (int j = 0; j < 4; j++) C[nt][j] = 0.f;

            #pragma unroll
            for (int s = 0; s < 4; s++) {
                #pragma unroll
                for (int nt = 0; nt < 8; nt++) {
                    uint4 bv = gsrc[(nt*4 + s)*32];
                    mma_f16(C[nt], AH[s], bv.x, bv.y);   // hi*hi
                    mma_f16(C[nt], AL[s], bv.x, bv.y);   // lo*hi
                    mma_f16(C[nt], AH[s], bv.z, bv.w);   // hi*lo
                }
            }

            // argmin epilogue: C cols 2tig, 2tig+1
            #pragma unroll
            for (int nt = 0; nt < 8; nt++) {
                int nb = ch*64 + nt*8 + 2*tig;
                float cq0 = csqS[nb], cq1 = csqS[nb + 1];
                float m00 = cq0 - 2.0f*C[nt][0];
                float m01 = cq1 - 2.0f*C[nt][1];
                float m10 = cq0 - 2.0f*C[nt][2];
                float m11 = cq1 - 2.0f*C[nt][3];
                if (m00 < best0) { best0 = m00; idx0 = nb; }
                if (m01 < best0) { best0 = m01; idx0 = nb + 1; }
                if (m10 < best1) { best1 = m10; idx1 = nb; }
                if (m11 < best1) { best1 = m11; idx1 = nb + 1; }
            }
        }

        // cross-lane argmin over the 4 lanes of the column group
        #pragma unroll
        for (int off = 1; off <= 2; off <<= 1) {
            float ov = __shfl_xor_sync(0xffffffffu, best0, off);
            int   oi = __shfl_xor_sync(0xffffffffu, idx0, off);
            if (ov < best0 || (ov == best0 && oi < idx0)) { best0 = ov; idx0 = oi; }
            ov = __shfl_xor_sync(0xffffffffu, best1, off);
            oi = __shfl_xor_sync(0xffffffffu, idx1, off);
            if (ov < best1 || (ov == best1 && oi < idx1)) { best1 = ov; idx1 = oi; }
        }
        if (tig == 0) {
            out[ZQ_OFF + q*NTOK + m0g] = (float)idx0;
            out[ZQ_OFF + q*NTOK + m1g] = (float)idx1;
        }

        // residual update + loss
        float ls = 0.f;
        {
            const float* cr0 = cb + ((size_t)q*BINS + idx0)*64;
            const float* cr1 = cb + ((size_t)q*BINS + idx1)*64;
            #pragma unroll
            for (int s = 0; s < 4; s++) {
                int ka = 16*s + 2*tig;
                float2 c0a = *(const float2*)(cr0 + ka);
                float2 c0b = *(const float2*)(cr0 + ka + 8);
                float2 c1a = *(const float2*)(cr1 + ka);
                float2 c1b = *(const float2*)(cr1 + ka + 8);
                float nv;
                nv = R0[s*4+0]-c0a.x; R0[s*4+0]=nv; ls += nv*nv;
                nv = R0[s*4+1]-c0a.y; R0[s*4+1]=nv; ls += nv*nv;
                nv = R0[s*4+2]-c0b.x; R0[s*4+2]=nv; ls += nv*nv;
                nv = R0[s*4+3]-c0b.y; R0[s*4+3]=nv; ls += nv*nv;
                nv = R1[s*4+0]-c1a.x; R1[s*4+0]=nv; ls += nv*nv;
                nv = R1[s*4+1]-c1a.y; R1[s*4+1]=nv; ls += nv*nv;
                nv = R1[s*4+2]-c1b.x; R1[s*4+2]=nv; ls += nv*nv;
                nv = R1[s*4+3]-c1b.y; R1[s*4+3]=nv; ls += nv*nv;
            }
        }
        #pragma unroll
        for (int o = 16; o; o >>= 1) ls += __shfl_xor_sync(0xffffffffu, ls, o);
        if (lane == 0) lossW[w] = ls;
        __syncthreads();
        if (tid == 0) {
            float s = 0.f;
            #pragma unroll
            for (int i = 0; i < 8; i++) s += lossW[i];
            atomicAdd(&g_loss[q], (double)s);
        }
        __syncthreads();
    }

    // -------- decode: QO = R_init - R_final; out = (QO @ dw^T + db)*spe + mean
    {
        float* qoS = sm + F_QO;
        const float* z0 = g_zh + (size_t)m0g*64;
        const float* z1 = g_zh + (size_t)m1g*64;
        #pragma unroll
        for (int s = 0; s < 4; s++) {
            int ka = 16*s + 2*tig;
            float2 a0 = *(const float2*)(z0 + ka);
            float2 b0 = *(const float2*)(z0 + ka + 8);
            float2 a1 = *(const float2*)(z1 + ka);
            float2 b1 = *(const float2*)(z1 + ka + 8);
            qoS[m0l*TPAD + ka]     = a0.x*invS[ka]   - R0[s*4+0];
            qoS[m0l*TPAD + ka + 1] = a0.y*invS[ka+1] - R0[s*4+1];
            qoS[m0l*TPAD + ka + 8] = b0.x*invS[ka+8] - R0[s*4+2];
            qoS[m0l*TPAD + ka + 9] = b0.y*invS[ka+9] - R0[s*4+3];
            qoS[m1l*TPAD + ka]     = a1.x*invS[ka]   - R1[s*4+0];
            qoS[m1l*TPAD + ka + 1] = a1.y*invS[ka+1] - R1[s*4+1];
            qoS[m1l*TPAD + ka + 8] = b1.x*invS[ka+8] - R1[s*4+2];
            qoS[m1l*TPAD + ka + 9] = b1.y*invS[ka+9] - R1[s*4+3];
        }
        float* dwS = sm + F_DW;
        #pragma unroll
        for (int i = 0; i < 16; i++) {
            int f = tid + i*256;
            int e = f >> 6, k = f & 63;
            dwS[e*TPAD + k] = dw[f];
        }
        __syncthreads();

        int ty = tid >> 4, tx = tid & 15;   // 16 token-groups x 16 e-lanes
        float acc[8][4];
        #pragma unroll
        for (int i = 0; i < 8; i++)
            #pragma unroll
            for (int j = 0; j < 4; j++) acc[i][j] = 0.f;
        #pragma unroll 8
        for (int k = 0; k < 64; k++) {
            float rv[8], cv[4];
            #pragma unroll
            for (int i = 0; i < 8; i++) rv[i] = qoS[(ty*8+i)*TPAD + k];
            #pragma unroll
            for (int j = 0; j < 4; j++) cv[j] = dwS[(j*16+tx)*TPAD + k];
            #pragma unroll
            for (int i = 0; i < 8; i++)
                #pragma unroll
                for (int j = 0; j < 4; j++) acc[i][j] += rv[i]*cv[j];
        }
        #pragma unroll
        for (int i = 0; i < 8; i++) {
            int t = t0 + ty*8 + i;
            int l = t & 63;
            float sp = speS[l], mm = meanS[l];
            #pragma unroll
            for (int j = 0; j < 4; j++) {
                int e = j*16 + tx;
                out[(size_t)t*64 + e] = (acc[i][j] + dbS[e])*sp + mm;
            }
        }
    }

    // -------- commit loss: last block to finish writes the scalar -------------
    __syncthreads();
    if (tid == 0) {
        __threadfence();
        unsigned done = atomicAdd(&g_done, 1u);
        if (done == 255u) {
            double s = 0.0;
            #pragma unroll
            for (int q = 0; q < NQ; q++) s += g_loss[q] / (double)(NTOK*DD);
            out[ZQ_OFF + CODES_N] = (float)(s / (double)NQ);
        }
    }
}

// ---------------- launch ------------------------------------------------------
extern "C" void kernel_launch(void* const* d_in, const int* in_sizes, int n_in,
                              void* d_out, int out_size) {
    const float* x    = (const float*)d_in[0];
    const float* ew   = (const float*)d_in[1];
    const float* eb   = (const float*)d_in[2];
    const float* dwp  = (const float*)d_in[3];
    const float* dbp  = (const float*)d_in[4];
    const float* cb   = (const float*)d_in[5];
    float* out = (float*)d_out;

    const int ENC_SMEM = (128*TPAD + 64*TPAD + 64*17 + 3*64) * 4;
    cudaFuncSetAttribute(k_enc, cudaFuncAttributeMaxDynamicSharedMemorySize, ENC_SMEM);
    cudaFuncSetAttribute(k_rvq, cudaFuncAttributeMaxDynamicSharedMemorySize, RVQ_SMEM);

    k_prep<<<512, 256>>>(cb);
    k_fft<<<BB*LL, 1024>>>(x);
    k_enc<<<256, 256, ENC_SMEM>>>(ew, eb);
    k_rvq<<<256, 256, RVQ_SMEM>>>(cb, dwp, dbp, out);
}

// round 17
// speedup vs baseline: 1.0915x; 1.0915x over previous
#include <cuda_runtime.h>
#include <cuda_fp16.h>
#include <math.h>
#include <stdint.h>

#define BB 32
#define VV 16
#define LL 64
#define PP 64
#define DD 64
#define NTOK 32768      // BB*VV*LL
#define NQ 8
#define BINS 1024
#define EPSF 1e-5f
#define TPAD 66

#define ZQ_OFF   (NTOK*DD)           // 2097152
#define CODES_N  (NQ*NTOK)           // 262144

typedef unsigned long long ull;

// m16n8k16 f16 mma, fp32 accum (sm_80+; legal under compute_100)
__device__ __forceinline__ void mma_f16(float* c, const uint32_t* a,
                                        uint32_t b0, uint32_t b1) {
    asm volatile("mma.sync.aligned.m16n8k16.row.col.f32.f16.f16.f32 "
        "{%0,%1,%2,%3}, {%4,%5,%6,%7}, {%8,%9}, {%0,%1,%2,%3};"
        : "+f"(c[0]), "+f"(c[1]), "+f"(c[2]), "+f"(c[3])
        : "r"(a[0]), "r"(a[1]), "r"(a[2]), "r"(a[3]), "r"(b0), "r"(b1));
}

__device__ __forceinline__ uint32_t pack_h2(float x, float y) {
    __half2 h = __floats2half2_rn(x, y);
    return *reinterpret_cast<uint32_t*>(&h);
}

// fp32x2 helpers for k_enc (lowered to 2x FFMA on sm_100; harmless)
__device__ __forceinline__ void fma2(ull& acc, ull a, ull b) {
    asm("fma.rn.f32x2 %0, %1, %2, %0;" : "+l"(acc) : "l"(a), "l"(b));
}
__device__ __forceinline__ float unpack_sum(ull a) {
    float2 p = *reinterpret_cast<float2*>(&a);
    return p.x + p.y;
}

// ---------------- scratch (device globals; no allocation allowed) -------------
__device__ __align__(16) float  g_z[NTOK*DD];
__device__ __align__(16) float  g_zh[NTOK*DD];
// fp16 hi/lo fragment codebook: F = (((q*16+ch)*8+nt)*4+s)*32+lane
// uint4 = {bhi0, bhi1, blo0, blo1}
__device__ __align__(16) uint4  g_cbf16[NQ*16*8*4*32];   // 131072 uint4
__device__ float    g_cbsq[NQ*BINS];
__device__ double   g_sum[LL], g_sumsq[LL];
__device__ double   g_colnorm[BB*DD];
__device__ double   g_loss[NQ];
__device__ unsigned g_done;

// ---------------- k_prep: codebook norms + fp16 fragments + zeroing -----------
__global__ void k_prep(const float* __restrict__ cb) {
    int tid = threadIdx.x;
    int F = blockIdx.x*256 + tid;
    {   // fp16 hi/lo fragment
        int lane = F & 31;
        int s    = (F >> 5) & 3;
        int nt   = (F >> 7) & 7;
        int ch   = (F >> 10) & 15;
        int q    = F >> 14;
        int g    = lane >> 2, tig = lane & 3;
        int entry = ch*64 + nt*8 + g;
        int k0 = 16*s + 2*tig;
        const float* src = cb + ((size_t)q*BINS + entry)*64;
        float v0 = src[k0],     v1 = src[k0+1];
        float v2 = src[k0+8],   v3 = src[k0+9];
        float h0 = __half2float(__float2half_rn(v0));
        float h1 = __half2float(__float2half_rn(v1));
        float h2 = __half2float(__float2half_rn(v2));
        float h3 = __half2float(__float2half_rn(v3));
        uint4 o;
        o.x = pack_h2(h0, h1);
        o.y = pack_h2(h2, h3);
        o.z = pack_h2(v0 - h0, v1 - h1);
        o.w = pack_h2(v2 - h2, v3 - h3);
        g_cbf16[F] = o;
    }
    if (blockIdx.x < 128) {   // squared norms, 64 rows/block, 4 thr/row
        int row = blockIdx.x*64 + (tid >> 2);
        const float* p = cb + (size_t)row*64 + (tid & 3)*16;
        float s = 0.f;
        #pragma unroll
        for (int i = 0; i < 16; i++) { float v = p[i]; s += v*v; }
        s += __shfl_xor_sync(0xffffffffu, s, 1);
        s += __shfl_xor_sync(0xffffffffu, s, 2);
        if ((tid & 3) == 0) g_cbsq[row] = s;
    }
    if (blockIdx.x < 8) g_colnorm[blockIdx.x*256 + tid] = 0.0;
    if (blockIdx.x == 0) {
        if (tid < LL) { g_sum[tid] = 0.0; g_sumsq[tid] = 0.0; }
        if (tid < NQ) g_loss[tid] = 0.0;
        if (tid == 0) g_done = 0u;
    }
}

// ---------------- k_fft: 64-pt DFT magnitude + fused per-l stats --------------
__global__ void __launch_bounds__(1024) k_fft(const float* __restrict__ x) {
    __shared__ float xs[PP*VV];
    __shared__ float ct[64], st[64];
    __shared__ float mags[VV*33];
    __shared__ float redp[64];
    int bi = blockIdx.x;
    int b = bi >> 6, l = bi & 63;
    int tid = threadIdx.x;
    xs[tid] = x[(size_t)(b*4096 + l*64)*16 + tid];
    if (tid < 64) { float a = (float)tid * (1.0f/32.0f); ct[tid] = cospif(a); st[tid] = sinpif(a); }
    __syncthreads();
    if (tid < 528) {
        int v = tid / 33, kk = tid % 33;
        float re = 0.f, im = 0.f;
        #pragma unroll 16
        for (int j = 0; j < 64; j++) {
            float val = xs[j*16 + v];
            int a = (j*kk) & 63;
            re += val * ct[a];
            im += val * st[a];
        }
        mags[v*33 + kk] = sqrtf(re*re + im*im);
    }
    __syncthreads();
    int v = tid >> 6, k = tid & 63;
    int kk = (k <= 32) ? k : (64 - k);
    float mag = mags[v*33 + kk];
    int t = (b*VV + v)*LL + l;
    g_z[t*64 + k] = mag;
    float s = mag, ss = mag*mag;
    #pragma unroll
    for (int o = 16; o; o >>= 1) {
        s  += __shfl_xor_sync(0xffffffffu, s, o);
        ss += __shfl_xor_sync(0xffffffffu, ss, o);
    }
    int wid = tid >> 5, lane = tid & 31;
    if (lane == 0) { redp[wid] = s; redp[32 + wid] = ss; }
    __syncthreads();
    if (tid < 32) {
        float s2 = redp[tid], ss2 = redp[32 + tid];
        #pragma unroll
        for (int o = 16; o; o >>= 1) {
            s2  += __shfl_xor_sync(0xffffffffu, s2, o);
            ss2 += __shfl_xor_sync(0xffffffffu, ss2, o);
        }
        if (tid == 0) {
            atomicAdd(&g_sum[l], (double)s2);
            atomicAdd(&g_sumsq[l], (double)ss2);
        }
    }
}

// helper: per-l mean / (std+eps) from accumulated double sums (ddof=1)
__device__ __forceinline__ void stat_ml(int l, float& mean_out, float& spe_out) {
    double n = 32768.0;
    double s = g_sum[l], ss = g_sumsq[l];
    double mean = s / n;
    double var = (ss - s*s/n) / (n - 1.0);
    mean_out = (float)mean;
    spe_out = (float)sqrt(var) + EPSF;
}

// ---------------- k_enc: encoder GEMM + per-(b,e) column norms ----------------
__global__ void __launch_bounds__(256, 2) k_enc(const float* __restrict__ ew,
                                                const float* __restrict__ eb) {
    extern __shared__ float sm[];
    float* zS   = sm;               // 128*TPAD
    float* wS   = zS + 128*TPAD;    // 64*TPAD
    float* red  = wS + 64*TPAD;     // 64*17
    float* meanS= red + 64*17;      // 64
    float* sinvS= meanS + 64;       // 64
    float* ebS  = sinvS + 64;       // 64

    int tid = threadIdx.x;
    int t0 = blockIdx.x * 128;

    if (tid < 64) {
        float mn, sp; stat_ml(tid, mn, sp);
        meanS[tid] = mn; sinvS[tid] = 1.0f / sp; ebS[tid] = eb[tid];
    }
    {
        const float4* w4 = (const float4*)ew;
        #pragma unroll
        for (int i = 0; i < 4; i++) {
            int f = tid + i*256;
            int e = f >> 4, d4 = f & 15;
            float4 v = w4[f];
            float* dst = wS + e*TPAD + d4*4;
            dst[0]=v.x; dst[1]=v.y; dst[2]=v.z; dst[3]=v.w;
        }
    }
    __syncthreads();
    {
        const float4* z4 = (const float4*)g_z + (size_t)t0*16;
        #pragma unroll
        for (int i = 0; i < 8; i++) {
            int f = tid + i*256;
            int t = f >> 4, d4 = f & 15;
            float4 v = z4[f];
            int l = (t0 + t) & 63;
            float m = meanS[l], si = sinvS[l];
            float* dst = zS + t*TPAD + d4*4;
            dst[0]=(v.x-m)*si; dst[1]=(v.y-m)*si; dst[2]=(v.z-m)*si; dst[3]=(v.w-m)*si;
        }
    }
    __syncthreads();

    int ty = tid >> 4, tx = tid & 15;
    ull acc2[8][4];
    #pragma unroll
    for (int i = 0; i < 8; i++)
        #pragma unroll
        for (int j = 0; j < 4; j++) acc2[i][j] = 0ull;

    #pragma unroll 8
    for (int d = 0; d < 64; d += 2) {
        ull rv[8], cv[4];
        #pragma unroll
        for (int i = 0; i < 8; i++) rv[i] = *(const ull*)(zS + (ty*8+i)*TPAD + d);
        #pragma unroll
        for (int j = 0; j < 4; j++) cv[j] = *(const ull*)(wS + (j*16+tx)*TPAD + d);
        #pragma unroll
        for (int i = 0; i < 8; i++)
            #pragma unroll
            for (int j = 0; j < 4; j++) fma2(acc2[i][j], rv[i], cv[j]);
    }

    float pn[4] = {0.f,0.f,0.f,0.f};
    #pragma unroll
    for (int i = 0; i < 8; i++) {
        int t = t0 + ty*8 + i;
        #pragma unroll
        for (int j = 0; j < 4; j++) {
            int e = j*16 + tx;
            float o = unpack_sum(acc2[i][j]) + ebS[e];
            pn[j] += o*o;
            g_zh[(size_t)t*64 + e] = o;
        }
    }
    #pragma unroll
    for (int j = 0; j < 4; j++) red[(j*16+tx)*17 + ty] = pn[j];
    __syncthreads();
    if (tid < 64) {
        float s = 0.f;
        #pragma unroll
        for (int y = 0; y < 16; y++) s += red[tid*17 + y];
        atomicAdd(&g_colnorm[(t0 >> 10)*64 + tid], (double)s);
    }
}

// ============================ k_rvq: fp16x3 mma RVQ ============================
// 128 blocks x 512 threads (16 warps); warp w owns token rows 16w..16w+15.
// Smem double-buffered staging (proven R14 path) but with 128-entry chunks:
// barrier once per 128 entries (9/stage vs 17) — thins the convoy while keeping
// LDS prefetch depth and C[8][4] register footprint (two sequential 64-entry
// halves share the accumulators; scan order identical -> bit-identical codes).

// smem float offsets (overlay: stage view / decode view)
#define F_BF    0                  // 16384 floats = 4096 uint4 (2 x 2048 buffers)
#define F_QO    0                  // decode: 256*66 = 16896
#define F_CSQ   16896              // 1024
#define F_DW    17920              // decode: 64*66 = 4224 -> ends 22144
#define F_FIX   22144
#define F_INV   (F_FIX)
#define F_MEAN  (F_FIX+64)
#define F_SPE   (F_FIX+128)
#define F_DB    (F_FIX+192)
#define F_LOSS  (F_FIX+256)        // 16
#define RVQ_SMEMF (F_FIX+272)
#define RVQ_SMEM  (RVQ_SMEMF*4)    // ~89.7 KB

__global__ void __launch_bounds__(512) k_rvq(const float* __restrict__ cb,
                                             const float* __restrict__ dw,
                                             const float* __restrict__ db,
                                             float* __restrict__ out) {
    extern __shared__ float sm[];
    uint4* bf4   = (uint4*)(sm + F_BF);
    float* csqS  = sm + F_CSQ;
    float* invS  = sm + F_INV;
    float* meanS = sm + F_MEAN;
    float* speS  = sm + F_SPE;
    float* dbS   = sm + F_DB;
    float* lossW = sm + F_LOSS;

    int tid = threadIdx.x;
    int w = tid >> 5, lane = tid & 31;
    int g = lane >> 2, tig = lane & 3;
    int t0 = blockIdx.x * 256;
    int b  = t0 >> 10;

    if (tid < 64) {
        invS[tid] = 1.0f / sqrtf((float)g_colnorm[b*64 + tid]);
        float mn, sp; stat_ml(tid, mn, sp);
        meanS[tid] = mn; speS[tid] = sp;
        dbS[tid]   = db[tid];
    }
    __syncthreads();

    int m0l = 16*w + g, m1l = m0l + 8;
    int m0g = t0 + m0l, m1g = t0 + m1l;

    // residual registers in A-fragment layout:
    // R[s*4+j]: k = 16s + 2tig + (j&1) + 8*(j>>1)
    float R0[16], R1[16];
    {
        const float* z0 = g_zh + (size_t)m0g*64;
        const float* z1 = g_zh + (size_t)m1g*64;
        #pragma unroll
        for (int s = 0; s < 4; s++) {
            int ka = 16*s + 2*tig;
            float2 a0 = *(const float2*)(z0 + ka);
            float2 b0 = *(const float2*)(z0 + ka + 8);
            float2 a1 = *(const float2*)(z1 + ka);
            float2 b1 = *(const float2*)(z1 + ka + 8);
            R0[s*4+0] = a0.x * invS[ka];     R0[s*4+1] = a0.y * invS[ka+1];
            R0[s*4+2] = b0.x * invS[ka+8];   R0[s*4+3] = b0.y * invS[ka+9];
            R1[s*4+0] = a1.x * invS[ka];     R1[s*4+1] = a1.y * invS[ka+1];
            R1[s*4+2] = b1.x * invS[ka+8];   R1[s*4+3] = b1.y * invS[ka+9];
        }
    }

    for (int q = 0; q < NQ; q++) {
        // A hi/lo fragments for this stage
        uint32_t AH[4][4], AL[4][4];
        #pragma unroll
        for (int s = 0; s < 4; s++) {
            float h00 = __half2float(__float2half_rn(R0[s*4+0]));
            float h01 = __half2float(__float2half_rn(R0[s*4+1]));
            float h02 = __half2float(__float2half_rn(R0[s*4+2]));
            float h03 = __half2float(__float2half_rn(R0[s*4+3]));
            float h10 = __half2float(__float2half_rn(R1[s*4+0]));
            float h11 = __half2float(__float2half_rn(R1[s*4+1]));
            float h12 = __half2float(__float2half_rn(R1[s*4+2]));
            float h13 = __half2float(__float2half_rn(R1[s*4+3]));
            AH[s][0] = pack_h2(h00, h01);
            AH[s][1] = pack_h2(h10, h11);
            AH[s][2] = pack_h2(h02, h03);
            AH[s][3] = pack_h2(h12, h13);
            AL[s][0] = pack_h2(R0[s*4+0]-h00, R0[s*4+1]-h01);
            AL[s][1] = pack_h2(R1[s*4+0]-h10, R1[s*4+1]-h11);
            AL[s][2] = pack_h2(R0[s*4+2]-h02, R0[s*4+3]-h03);
            AL[s][3] = pack_h2(R1[s*4+2]-h12, R1[s*4+3]-h13);
        }

        __syncthreads();   // previous-iteration smem consumers done
        csqS[tid]       = g_cbsq[q*BINS + tid];
        csqS[tid + 512] = g_cbsq[q*BINS + tid + 512];
        {   // prefill chunk-pair 0 into buf 0 (2048 uint4 / 512 threads)
            const uint4* src = g_cbf16 + (size_t)q*16*1024;
            #pragma unroll
            for (int i = 0; i < 4; i++) bf4[tid + i*512] = src[tid + i*512];
        }
        __syncthreads();

        float best0 = INFINITY, best1 = INFINITY;
        int idx0 = 0, idx1 = 0;

        for (int ch2 = 0; ch2 < 8; ch2++) {       // 128-entry chunk pairs
            if (ch2 < 7) {   // prefetch next pair into other buffer
                const uint4* src = g_cbf16 + (size_t)(q*16 + (ch2+1)*2)*1024;
                uint4* dst = bf4 + ((ch2 + 1) & 1)*2048;
                #pragma unroll
                for (int i = 0; i < 4; i++) dst[tid + i*512] = src[tid + i*512];
            }
            #pragma unroll
            for (int half = 0; half < 2; half++) {
                const uint4* buf = bf4 + (ch2 & 1)*2048 + half*1024;

                float C[8][4];
                #pragma unroll
                for (int nt = 0; nt < 8; nt++)
                    #pragma unroll
                    for (int j = 0; j < 4; j++) C[nt][j] = 0.f;

                #pragma unroll
                for (int s = 0; s < 4; s++) {
                    #pragma unroll
                    for (int nt = 0; nt < 8; nt++) {
                        uint4 bv = buf[(nt*4 + s)*32 + lane];
                        mma_f16(C[nt], AH[s], bv.x, bv.y);   // hi*hi
                        mma_f16(C[nt], AL[s], bv.x, bv.y);   // lo*hi
                        mma_f16(C[nt], AH[s], bv.z, bv.w);   // hi*lo
                    }
                }

                // argmin epilogue: C cols 2tig, 2tig+1
                int ch = ch2*2 + half;
                #pragma unroll
                for (int nt = 0; nt < 8; nt++) {
                    int nb = ch*64 + nt*8 + 2*tig;
                    float cq0 = csqS[nb], cq1 = csqS[nb + 1];
                    float m00 = cq0 - 2.0f*C[nt][0];
                    float m01 = cq1 - 2.0f*C[nt][1];
                    float m10 = cq0 - 2.0f*C[nt][2];
                    float m11 = cq1 - 2.0f*C[nt][3];
                    if (m00 < best0) { best0 = m00; idx0 = nb; }
                    if (m01 < best0) { best0 = m01; idx0 = nb + 1; }
                    if (m10 < best1) { best1 = m10; idx1 = nb; }
                    if (m11 < best1) { best1 = m11; idx1 = nb + 1; }
                }
            }
            __syncthreads();   // all warps done with buf[ch2&1] before refill
        }

        // cross-lane argmin over the 4 lanes of the column group
        #pragma unroll
        for (int off = 1; off <= 2; off <<= 1) {
            float ov = __shfl_xor_sync(0xffffffffu, best0, off);
            int   oi = __shfl_xor_sync(0xffffffffu, idx0, off);
            if (ov < best0 || (ov == best0 && oi < idx0)) { best0 = ov; idx0 = oi; }
            ov = __shfl_xor_sync(0xffffffffu, best1, off);
            oi = __shfl_xor_sync(0xffffffffu, idx1, off);
            if (ov < best1 || (ov == best1 && oi < idx1)) { best1 = ov; idx1 = oi; }
        }
        if (tig == 0) {
            out[ZQ_OFF + q*NTOK + m0g] = (float)idx0;
            out[ZQ_OFF + q*NTOK + m1g] = (float)idx1;
        }

        // residual update + loss
        float ls = 0.f;
        {
            const float* cr0 = cb + ((size_t)q*BINS + idx0)*64;
            const float* cr1 = cb + ((size_t)q*BINS + idx1)*64;
            #pragma unroll
            for (int s = 0; s < 4; s++) {
                int ka = 16*s + 2*tig;
                float2 c0a = *(const float2*)(cr0 + ka);
                float2 c0b = *(const float2*)(cr0 + ka + 8);
                float2 c1a = *(const float2*)(cr1 + ka);
                float2 c1b = *(const float2*)(cr1 + ka + 8);
                float nv;
                nv = R0[s*4+0]-c0a.x; R0[s*4+0]=nv; ls += nv*nv;
                nv = R0[s*4+1]-c0a.y; R0[s*4+1]=nv; ls += nv*nv;
                nv = R0[s*4+2]-c0b.x; R0[s*4+2]=nv; ls += nv*nv;
                nv = R0[s*4+3]-c0b.y; R0[s*4+3]=nv; ls += nv*nv;
                nv = R1[s*4+0]-c1a.x; R1[s*4+0]=nv; ls += nv*nv;
                nv = R1[s*4+1]-c1a.y; R1[s*4+1]=nv; ls += nv*nv;
                nv = R1[s*4+2]-c1b.x; R1[s*4+2]=nv; ls += nv*nv;
                nv = R1[s*4+3]-c1b.y; R1[s*4+3]=nv; ls += nv*nv;
            }
        }
        #pragma unroll
        for (int o = 16; o; o >>= 1) ls += __shfl_xor_sync(0xffffffffu, ls, o);
        if (lane == 0) lossW[w] = ls;
        __syncthreads();
        if (tid == 0) {
            float s = 0.f;
            #pragma unroll
            for (int i = 0; i < 16; i++) s += lossW[i];
            atomicAdd(&g_loss[q], (double)s);
        }
        __syncthreads();
    }

    // -------- decode: QO = R_init - R_final; out = (QO @ dw^T + db)*spe + mean
    {
        float* qoS = sm + F_QO;
        const float* z0 = g_zh + (size_t)m0g*64;
        const float* z1 = g_zh + (size_t)m1g*64;
        #pragma unroll
        for (int s = 0; s < 4; s++) {
            int ka = 16*s + 2*tig;
            float2 a0 = *(const float2*)(z0 + ka);
            float2 b0 = *(const float2*)(z0 + ka + 8);
            float2 a1 = *(const float2*)(z1 + ka);
            float2 b1 = *(const float2*)(z1 + ka + 8);
            qoS[m0l*TPAD + ka]     = a0.x*invS[ka]   - R0[s*4+0];
            qoS[m0l*TPAD + ka + 1] = a0.y*invS[ka+1] - R0[s*4+1];
            qoS[m0l*TPAD + ka + 8] = b0.x*invS[ka+8] - R0[s*4+2];
            qoS[m0l*TPAD + ka + 9] = b0.y*invS[ka+9] - R0[s*4+3];
            qoS[m1l*TPAD + ka]     = a1.x*invS[ka]   - R1[s*4+0];
            qoS[m1l*TPAD + ka + 1] = a1.y*invS[ka+1] - R1[s*4+1];
            qoS[m1l*TPAD + ka + 8] = b1.x*invS[ka+8] - R1[s*4+2];
            qoS[m1l*TPAD + ka + 9] = b1.y*invS[ka+9] - R1[s*4+3];
        }
        float* dwS = sm + F_DW;
        #pragma unroll
        for (int i = 0; i < 8; i++) {
            int f = tid + i*512;
            int e = f >> 6, k = f & 63;
            dwS[e*TPAD + k] = dw[f];
        }
        __syncthreads();

        int ty = tid >> 4, tx = tid & 15;   // 32 token-groups x 16 e-lanes
        float acc[8][4];
        #pragma unroll
        for (int i = 0; i < 8; i++)
            #pragma unroll
            for (int j = 0; j < 4; j++) acc[i][j] = 0.f;
        #pragma unroll 8
        for (int k = 0; k < 64; k++) {
            float rv[8], cv[4];
            #pragma unroll
            for (int i = 0; i < 8; i++) rv[i] = qoS[(ty*8+i)*TPAD + k];
            #pragma unroll
            for (int j = 0; j < 4; j++) cv[j] = dwS[(j*16+tx)*TPAD + k];
            #pragma unroll
            for (int i = 0; i < 8; i++)
                #pragma unroll
                for (int j = 0; j < 4; j++) acc[i][j] += rv[i]*cv[j];
        }
        #pragma unroll
        for (int i = 0; i < 8; i++) {
            int t = t0 + ty*8 + i;
            int l = t & 63;
            float sp = speS[l], mm = meanS[l];
            #pragma unroll
            for (int j = 0; j < 4; j++) {
                int e = j*16 + tx;
                out[(size_t)t*64 + e] = (acc[i][j] + dbS[e])*sp + mm;
            }
        }
    }

    // -------- commit loss: last block to finish writes the scalar -------------
    __syncthreads();
    if (tid == 0) {
        __threadfence();
        unsigned done = atomicAdd(&g_done, 1u);
        if (done == 127u) {
            double s = 0.0;
            #pragma unroll
            for (int q = 0; q < NQ; q++) s += g_loss[q] / (double)(NTOK*DD);
            out[ZQ_OFF + CODES_N] = (float)(s / (double)NQ);
        }
    }
}

// ---------------- launch ------------------------------------------------------
extern "C" void kernel_launch(void* const* d_in, const int* in_sizes, int n_in,
                              void* d_out, int out_size) {
    const float* x    = (const float*)d_in[0];
    const float* ew   = (const float*)d_in[1];
    const float* eb   = (const float*)d_in[2];
    const float* dwp  = (const float*)d_in[3];
    const float* dbp  = (const float*)d_in[4];
    const float* cb   = (const float*)d_in[5];
    float* out = (float*)d_out;

    const int ENC_SMEM = (128*TPAD + 64*TPAD + 64*17 + 3*64) * 4;
    cudaFuncSetAttribute(k_enc, cudaFuncAttributeMaxDynamicSharedMemorySize, ENC_SMEM);
    cudaFuncSetAttribute(k_rvq, cudaFuncAttributeMaxDynamicSharedMemorySize, RVQ_SMEM);

    k_prep<<<512, 256>>>(cb);
    k_fft<<<BB*LL, 1024>>>(x);
    k_enc<<<256, 256, ENC_SMEM>>>(ew, eb);
    k_rvq<<<128, 512, RVQ_SMEM>>>(cb, dwp, dbp, out);
}